// round 13
// baseline (speedup 1.0000x reference)
#include <cuda_runtime.h>
#include <math.h>

// Elman RNN, fp32. B=128, S=1024, I=256, H=512, O=256, N_TARGETS=1.
// Phase A: P[t][j][b] fma2-packed GEMM (measured 722us).
// Phase B: R4 persistent k-split recurrence, SAME algorithm/layout/barriers,
//          but 512 threads/CTA (16 warps/SM) for latency hiding. Scalar FFMA
//          (fma2 proven pipe-neutral and harmful here).
// Phase C: output projection + hidden emit (R4 verbatim).

typedef unsigned long long ull;

namespace {
constexpr int S = 1024, B = 128, I = 256, H = 512, O = 256;
constexpr int G = 128;    // persistent grid
constexpr int KT = 16;    // k chunks
constexpr int KC = 32;    // chunk size
constexpr int JC = 128;   // j tile
}

__device__ float g_P[(size_t)S * H * B];      // [t][j][b] pre-activations
__device__ float g_Ht[H * B];                 // hidden state [k][b]
__device__ float g_Part[(size_t)KT * H * B];  // k-split partials [kk][j][b]
__device__ unsigned g_arrive;                 // grid barrier counter

__device__ __forceinline__ ull pack2(float x) {
    ull r;
    asm("mov.b64 %0, {%1, %1};" : "=l"(r) : "f"(x));
    return r;
}
__device__ __forceinline__ float2 unpack2(ull v) {
    float2 r;
    asm("mov.b64 {%0, %1}, %2;" : "=f"(r.x), "=f"(r.y) : "l"(v));
    return r;
}
__device__ __forceinline__ void fma2(ull& d, ull a, ull b) {
    asm("fma.rn.f32x2 %0, %1, %2, %0;" : "+l"(d) : "l"(a), "l"(b));
}

__device__ __forceinline__ void grid_barrier(unsigned target) {
    __syncthreads();
    if (threadIdx.x == 0) {
        __threadfence();
        atomicAdd(&g_arrive, 1u);
        unsigned v;
        do {
            asm volatile("ld.acquire.gpu.u32 %0, [%1];"
                         : "=r"(v) : "l"(&g_arrive) : "memory");
        } while (v < target);
    }
    __syncthreads();
}

// ---------------- Phase A: pre-activation GEMM (fma2, measured 722us) -------
// grid (S, H/128), 256 threads. CTA: 128 j x 128 b for one t, K=I=256.
__global__ void __launch_bounds__(256) phaseA_kernel(
    const float* __restrict__ seq, const float* __restrict__ Wi2h,
    const float* __restrict__ bi2h) {
    const int t = blockIdx.x;
    const int j0 = blockIdx.y * 128;
    const int tid = threadIdx.x;
    const int tx = tid & 15;   // 8 b per thread
    const int ty = tid >> 4;   // 8 j per thread (4 fma2 pairs)
    __shared__ float sh_a[16 * 132];  // [k][j], padded
    __shared__ float sh_b[16 * 132];  // [k][b], padded
    ull acc[4][8];
#pragma unroll
    for (int r = 0; r < 4; r++)
#pragma unroll
        for (int c = 0; c < 8; c++) acc[r][c] = 0;

    for (int k0 = 0; k0 < I; k0 += 16) {
        __syncthreads();
#pragma unroll
        for (int q = 0; q < 2; q++) {
            int idx = tid + q * 256;  // 0..511
            int j = idx >> 2, kq = idx & 3;
            float4 v = *(const float4*)(Wi2h + (size_t)(j0 + j) * (I + H) + k0 + kq * 4);
            sh_a[(kq * 4 + 0) * 132 + j] = v.x;
            sh_a[(kq * 4 + 1) * 132 + j] = v.y;
            sh_a[(kq * 4 + 2) * 132 + j] = v.z;
            sh_a[(kq * 4 + 3) * 132 + j] = v.w;
        }
#pragma unroll
        for (int q = 0; q < 2; q++) {
            int idx = tid + q * 256;
            int b = idx >> 2, kq = idx & 3;
            float4 v = *(const float4*)(seq + (size_t)b * (S * I) + (size_t)t * I + k0 + kq * 4);
            sh_b[(kq * 4 + 0) * 132 + b] = v.x;
            sh_b[(kq * 4 + 1) * 132 + b] = v.y;
            sh_b[(kq * 4 + 2) * 132 + b] = v.z;
            sh_b[(kq * 4 + 3) * 132 + b] = v.w;
        }
        __syncthreads();
#pragma unroll
        for (int k = 0; k < 16; k++) {
            ulonglong2 a01 = *(const ulonglong2*)(sh_a + k * 132 + ty * 8);
            ulonglong2 a23 = *(const ulonglong2*)(sh_a + k * 132 + ty * 8 + 4);
            float4 b0 = *(const float4*)(sh_b + k * 132 + tx * 8);
            float4 b1 = *(const float4*)(sh_b + k * 132 + tx * 8 + 4);
            ull bb[8] = {pack2(b0.x), pack2(b0.y), pack2(b0.z), pack2(b0.w),
                         pack2(b1.x), pack2(b1.y), pack2(b1.z), pack2(b1.w)};
#pragma unroll
            for (int c = 0; c < 8; c++) {
                fma2(acc[0][c], a01.x, bb[c]);
                fma2(acc[1][c], a01.y, bb[c]);
                fma2(acc[2][c], a23.x, bb[c]);
                fma2(acc[3][c], a23.y, bb[c]);
            }
        }
    }
    // epilogue: unpack j-pairs, add bias, write P[t][j][b]
#pragma unroll
    for (int r = 0; r < 4; r++) {
        int j = j0 + ty * 8 + r * 2;
        float bj0 = bi2h[j], bj1 = bi2h[j + 1];
        float lo[8], hi[8];
#pragma unroll
        for (int c = 0; c < 8; c++) {
            float2 f = unpack2(acc[r][c]);
            lo[c] = f.x + bj0;
            hi[c] = f.y + bj1;
        }
        float* op0 = g_P + (size_t)t * (H * B) + (size_t)j * B + tx * 8;
        float* op1 = op0 + B;
        *(float4*)op0 = make_float4(lo[0], lo[1], lo[2], lo[3]);
        *(float4*)(op0 + 4) = make_float4(lo[4], lo[5], lo[6], lo[7]);
        *(float4*)op1 = make_float4(hi[0], hi[1], hi[2], hi[3]);
        *(float4*)(op1 + 4) = make_float4(hi[4], hi[5], hi[6], hi[7]);
    }
}

// ---------------- Phase B: R4 algorithm @ 512 threads/CTA -------------------
// 128 CTAs = 2 batch-halves x 4 j-tiles(128) x 16 k-chunks(32).
// Per step: stage1 partial GEMM -> barrier -> stage2 reduce+tanh -> barrier.
// Thread tile 4b x 4j (16 FFMA + 2 LDS.128 per k); 16 warps/SM hide latency.
__global__ void __launch_bounds__(512) phaseB_kernel(const float* __restrict__ Wi2h) {
    const int cta = blockIdx.x;
    const int kk = cta & 15;
    const int jj = (cta >> 4) & 3;
    const int bb = cta >> 6;
    const int k0 = kk * KC;
    const int j0 = jj * JC;
    const int b0 = bb * 64;
    const int tid = threadIdx.x;
    const int tx = tid & 15;  // 4 b per thread
    const int ty = tid >> 4;  // 0..31 -> 4 j per thread
    __shared__ float sh_w[KC * JC];  // [k][j] 16KB, persistent across steps
    __shared__ float sh_h[KC * 64];  // [k][b] 8KB, restaged each step

    // Load Wh tile once: Wh[k][j] = Wi2h[(j0+j)*(I+H) + I + k0 + k]
#pragma unroll
    for (int q = 0; q < 2; q++) {
        int idx = tid + q * 512;  // 0..1023 float4 slots
        int j = idx >> 3, kq = idx & 7;
        float4 v = *(const float4*)(Wi2h + (size_t)(j0 + j) * (I + H) + I + k0 + kq * 4);
        sh_w[(kq * 4 + 0) * JC + j] = v.x;
        sh_w[(kq * 4 + 1) * JC + j] = v.y;
        sh_w[(kq * 4 + 2) * JC + j] = v.z;
        sh_w[(kq * 4 + 3) * JC + j] = v.w;
    }

    unsigned bar = 0;
    for (int t = 0; t < S; t++) {
        // stage 1: stage h chunk [k0..k0+32) x [b0..b0+64) into smem
        {
            int k = tid >> 4, bq = tid & 15;  // 512 float4 slots, one round
            *(float4*)(sh_h + k * 64 + bq * 4) =
                *(const float4*)(g_Ht + (k0 + k) * B + b0 + bq * 4);
        }
        __syncthreads();
        float acc[4][4];  // [b][j]
#pragma unroll
        for (int r = 0; r < 4; r++)
#pragma unroll
            for (int c = 0; c < 4; c++) acc[r][c] = 0.f;
#pragma unroll 8
        for (int k = 0; k < KC; k++) {
            float4 hv = *(const float4*)(sh_h + k * 64 + tx * 4);
            float4 wv = *(const float4*)(sh_w + k * JC + ty * 4);
            float hvv[4] = {hv.x, hv.y, hv.z, hv.w};
            float wvv[4] = {wv.x, wv.y, wv.z, wv.w};
#pragma unroll
            for (int r = 0; r < 4; r++)
#pragma unroll
                for (int c = 0; c < 4; c++) acc[r][c] = fmaf(hvv[r], wvv[c], acc[r][c]);
        }
        {
            float* pp = g_Part + (size_t)kk * (H * B) + (size_t)(j0 + ty * 4) * B + b0 + tx * 4;
#pragma unroll
            for (int c = 0; c < 4; c++) {
                float4 v = {acc[0][c], acc[1][c], acc[2][c], acc[3][c]};
                *(float4*)(pp + c * B) = v;
            }
        }
        grid_barrier(++bar * G);

        // stage 2: reduce KT partials + pre-activation, tanh, write new Ht
        {
            int o = cta * 512 + tid;  // one output per thread
            const float* pP = g_P + (size_t)t * (H * B);
            float a0 = pP[o];
#pragma unroll
            for (int q = 0; q < KT; q++) a0 += g_Part[(size_t)q * (H * B) + o];
            g_Ht[o] = tanhf(a0);
        }
        grid_barrier(++bar * G);
    }
}

// ---------------- Phase C: output projection + hidden emit (R4) -------------
__global__ void __launch_bounds__(256) phaseC_kernel(
    const float* __restrict__ Wh2o, const float* __restrict__ bh2o,
    float* __restrict__ out, int out_size) {
    int idx = blockIdx.x * 256 + threadIdx.x;  // 0..32767
    int b = idx >> 8, o = idx & 255;
    float acc = bh2o[o];
    const float4* wrow = (const float4*)(Wh2o + (size_t)o * H);
#pragma unroll 4
    for (int k4 = 0; k4 < H / 4; k4++) {
        float4 w = wrow[k4];
        int kb = k4 * 4;
        acc = fmaf(g_Ht[(kb + 0) * B + b], w.x, acc);
        acc = fmaf(g_Ht[(kb + 1) * B + b], w.y, acc);
        acc = fmaf(g_Ht[(kb + 2) * B + b], w.z, acc);
        acc = fmaf(g_Ht[(kb + 3) * B + b], w.w, acc);
    }
    if (idx < out_size) out[idx] = acc;  // output (B,1,O): idx = b*256+o
    if (out_size >= B * O + B * H) {
#pragma unroll
        for (int q = 0; q < 2; q++) {
            int e = idx + q * (B * O);  // 0..65535
            int hb = e >> 9, hk = e & 511;
            out[B * O + e] = g_Ht[hk * B + hb];
        }
    }
}

extern "C" void kernel_launch(void* const* d_in, const int* in_sizes, int n_in,
                              void* d_out, int out_size) {
    const float* seq  = (const float*)d_in[0];
    const float* Wi2h = (const float*)d_in[1];
    const float* bi2h = (const float*)d_in[2];
    const float* Wh2o = (const float*)d_in[3];
    const float* bh2o = (const float*)d_in[4];
    float* out = (float*)d_out;

    void* pArr = nullptr;
    cudaGetSymbolAddress(&pArr, g_arrive);
    cudaMemsetAsync(pArr, 0, sizeof(unsigned), 0);
    void* pHt = nullptr;
    cudaGetSymbolAddress(&pHt, g_Ht);
    cudaMemsetAsync(pHt, 0, (size_t)H * B * sizeof(float), 0);

    phaseA_kernel<<<dim3(S, H / 128), 256>>>(seq, Wi2h, bi2h);
    phaseB_kernel<<<G, 512>>>(Wi2h);
    phaseC_kernel<<<(B * O) / 256, 256>>>(Wh2o, bh2o, out, out_size);
}

// round 14
// speedup vs baseline: 1.3859x; 1.3859x over previous
#include <cuda_runtime.h>
#include <math.h>

// Elman RNN, fp32. B=128, S=1024, I=256, H=512, O=256, N_TARGETS=1.
// Phase A: P[t][j][b] fma2-packed GEMM (measured 722us, 3x).
// Phase B: Round-4's k-slice-warp recurrence (measured 4.02ms): 128 CTAs =
//          8 j-tiles(64j) x 16 b-groups(8b); w_s[512k][64j] smem-resident;
//          warp = 64-k slice, thread 8j x 2b fma2; p_s smem partials;
//          double-buffered g_Hbuf[k][b]; one 8-arrival release/acquire
//          group barrier per step.
// Phase C: output projection + hidden emit (Round-4 verbatim).

typedef unsigned long long ull;

namespace {
constexpr int S = 1024, B = 128, I = 256, H = 512, O = 256;
constexpr int NJ = 8, NB = 16;      // j-tiles per group, b-tiles (128 CTAs)
constexpr int JT = 64, BT = 8;      // CTA tile
constexpr int KZ = 8;               // k-slices (one per warp)
constexpr int KSL = H / KZ;         // 64
constexpr int PBS = 70;             // partial b-row stride (floats)
constexpr int PB = BT * PBS;        // 560 floats per kz plane
constexpr int W_S_FLOATS = H * JT;  // 32768 (128 KB)
constexpr int H_S_FLOATS = H * BT;  // 4096  (16 KB)
constexpr int P_S_FLOATS = KZ * PB; // 4480  (17.5 KB)
constexpr int SMEM_B_BYTES = (W_S_FLOATS + H_S_FLOATS + P_S_FLOATS) * 4;
}

__device__ float g_P[(size_t)S * H * B];   // [t][j][b] pre-activations (256 MB)
__device__ float g_Hbuf[2][H * B];         // ping-pong hidden state [k][b]
__device__ struct { unsigned v; unsigned pad[31]; } g_bar[NB];

__device__ __forceinline__ ull pack2(float x) {
    ull r;
    asm("mov.b64 %0, {%1, %1};" : "=l"(r) : "f"(x));
    return r;
}
__device__ __forceinline__ float2 unpack2(ull v) {
    float2 r;
    asm("mov.b64 {%0, %1}, %2;" : "=f"(r.x), "=f"(r.y) : "l"(v));
    return r;
}
__device__ __forceinline__ void fma2(ull& d, ull a, ull b) {
    asm("fma.rn.f32x2 %0, %1, %2, %0;" : "+l"(d) : "l"(a), "l"(b));
}

// ---------------- Phase A: pre-activation GEMM (fma2, measured 722us) -------
// grid (S, H/128), 256 threads. CTA: 128 j x 128 b for one t, K=I=256.
__global__ void __launch_bounds__(256) phaseA_kernel(
    const float* __restrict__ seq, const float* __restrict__ Wi2h,
    const float* __restrict__ bi2h) {
    const int t = blockIdx.x;
    const int j0 = blockIdx.y * 128;
    const int tid = threadIdx.x;
    const int tx = tid & 15;   // 8 b per thread
    const int ty = tid >> 4;   // 8 j per thread (4 fma2 pairs)
    __shared__ float sh_a[16 * 132];  // [k][j], padded
    __shared__ float sh_b[16 * 132];  // [k][b], padded
    ull acc[4][8];
#pragma unroll
    for (int r = 0; r < 4; r++)
#pragma unroll
        for (int c = 0; c < 8; c++) acc[r][c] = 0;

    for (int k0 = 0; k0 < I; k0 += 16) {
        __syncthreads();
#pragma unroll
        for (int q = 0; q < 2; q++) {
            int idx = tid + q * 256;  // 0..511
            int j = idx >> 2, kq = idx & 3;
            float4 v = *(const float4*)(Wi2h + (size_t)(j0 + j) * (I + H) + k0 + kq * 4);
            sh_a[(kq * 4 + 0) * 132 + j] = v.x;
            sh_a[(kq * 4 + 1) * 132 + j] = v.y;
            sh_a[(kq * 4 + 2) * 132 + j] = v.z;
            sh_a[(kq * 4 + 3) * 132 + j] = v.w;
        }
#pragma unroll
        for (int q = 0; q < 2; q++) {
            int idx = tid + q * 256;
            int b = idx >> 2, kq = idx & 3;
            float4 v = *(const float4*)(seq + (size_t)b * (S * I) + (size_t)t * I + k0 + kq * 4);
            sh_b[(kq * 4 + 0) * 132 + b] = v.x;
            sh_b[(kq * 4 + 1) * 132 + b] = v.y;
            sh_b[(kq * 4 + 2) * 132 + b] = v.z;
            sh_b[(kq * 4 + 3) * 132 + b] = v.w;
        }
        __syncthreads();
#pragma unroll
        for (int k = 0; k < 16; k++) {
            ulonglong2 a01 = *(const ulonglong2*)(sh_a + k * 132 + ty * 8);
            ulonglong2 a23 = *(const ulonglong2*)(sh_a + k * 132 + ty * 8 + 4);
            float4 b0 = *(const float4*)(sh_b + k * 132 + tx * 8);
            float4 b1 = *(const float4*)(sh_b + k * 132 + tx * 8 + 4);
            ull bb[8] = {pack2(b0.x), pack2(b0.y), pack2(b0.z), pack2(b0.w),
                         pack2(b1.x), pack2(b1.y), pack2(b1.z), pack2(b1.w)};
#pragma unroll
            for (int c = 0; c < 8; c++) {
                fma2(acc[0][c], a01.x, bb[c]);
                fma2(acc[1][c], a01.y, bb[c]);
                fma2(acc[2][c], a23.x, bb[c]);
                fma2(acc[3][c], a23.y, bb[c]);
            }
        }
    }
    // epilogue: unpack j-pairs, add bias, write P[t][j][b]
#pragma unroll
    for (int r = 0; r < 4; r++) {
        int j = j0 + ty * 8 + r * 2;
        float bj0 = bi2h[j], bj1 = bi2h[j + 1];
        float lo[8], hi[8];
#pragma unroll
        for (int c = 0; c < 8; c++) {
            float2 f = unpack2(acc[r][c]);
            lo[c] = f.x + bj0;
            hi[c] = f.y + bj1;
        }
        float* op0 = g_P + (size_t)t * (H * B) + (size_t)j * B + tx * 8;
        float* op1 = op0 + B;
        *(float4*)op0 = make_float4(lo[0], lo[1], lo[2], lo[3]);
        *(float4*)(op0 + 4) = make_float4(lo[4], lo[5], lo[6], lo[7]);
        *(float4*)op1 = make_float4(hi[0], hi[1], hi[2], hi[3]);
        *(float4*)(op1 + 4) = make_float4(hi[4], hi[5], hi[6], hi[7]);
    }
}

// ---------------- Phase B: Round-4 persistent recurrence (measured 4.02ms) --
__global__ void __launch_bounds__(256) phaseB_kernel(const float* __restrict__ Wi2h) {
    extern __shared__ float smem[];
    float* w_s = smem;                       // [512 k][64 j]
    float* h_s = smem + W_S_FLOATS;          // [512 k][8 b]
    float* p_s = h_s + H_S_FLOATS;           // [8 kz][8 b (stride 70)][64 j]

    const int bb = blockIdx.x & 15;          // b-group / barrier group
    const int jj = blockIdx.x >> 4;          // j-tile
    const int j0 = jj * JT;
    const int b0 = bb * BT;
    const int tid = threadIdx.x;
    const int kz = tid >> 5;                 // warp id = k-slice
    const int lane = tid & 31;
    const int ty = lane >> 2;                // 0..7  -> j = ty*8 .. +8
    const int tx = lane & 3;                 // 0..3  -> b = tx*2, tx*2+1

    // Load Wh transposed into w_s[k][j]:  Wh[k][j] = Wi2h[(j0+j)*(I+H)+I+k]
#pragma unroll
    for (int q = 0; q < 32; q++) {
        int idx = tid + q * 256;             // 0..8191 float4 slots
        int j = idx >> 7, k4 = idx & 127;
        float4 v = *(const float4*)(Wi2h + (size_t)(j0 + j) * (I + H) + I + k4 * 4);
        w_s[(k4 * 4 + 0) * JT + j] = v.x;
        w_s[(k4 * 4 + 1) * JT + j] = v.y;
        w_s[(k4 * 4 + 2) * JT + j] = v.z;
        w_s[(k4 * 4 + 3) * JT + j] = v.w;
    }

    unsigned* ctr = &g_bar[bb].v;
    const int jl1 = tid >> 3;                // reducer output 1: j local 0..31
    const int jl2 = 32 + jl1;                // reducer output 2: j local 32..63
    const int bl = tid & 7;

    const float* wp = w_s + kz * KSL * JT + ty * 8;
    const float* hp = h_s + kz * KSL * BT + tx * 2;

    for (int t = 0; t < S; t++) {
        const float* rbuf = g_Hbuf[t & 1];
        float* wbuf = g_Hbuf[(t + 1) & 1];

        // P prefetch (DRAM latency hidden under compute)
        const float* pP = g_P + (size_t)t * (H * B) + (size_t)j0 * B + b0;
        float p1 = pP[jl1 * B + bl];
        float p2 = pP[jl2 * B + bl];

        // stage h slice: h_s[k][b] <- rbuf[k][b0..b0+8)   (conflict-free STS.128)
#pragma unroll
        for (int q = 0; q < 4; q++) {
            int idx = tid + q * 256;         // 0..1023
            int k = idx >> 1, half = idx & 1;
            float4 v = *(const float4*)(rbuf + k * B + b0 + half * 4);
            *(float4*)(h_s + k * BT + half * 4) = v;
        }
        __syncthreads();

        // main k-slice loop: 8j x 2b per thread, packed f32x2 FMA
        ull acc00 = 0, acc01 = 0, acc10 = 0, acc11 = 0;
        ull acc20 = 0, acc21 = 0, acc30 = 0, acc31 = 0;
#pragma unroll 8
        for (int kk = 0; kk < KSL; kk++) {
            ulonglong2 wA = *(const ulonglong2*)(wp + kk * JT);
            ulonglong2 wB = *(const ulonglong2*)(wp + kk * JT + 4);
            float2 hv = *(const float2*)(hp + kk * BT);
            ull h0 = pack2(hv.x);
            ull h1 = pack2(hv.y);
            fma2(acc00, wA.x, h0); fma2(acc01, wA.x, h1);
            fma2(acc10, wA.y, h0); fma2(acc11, wA.y, h1);
            fma2(acc20, wB.x, h0); fma2(acc21, wB.x, h1);
            fma2(acc30, wB.y, h0); fma2(acc31, wB.y, h1);
        }

        // store partials: p_s[kz][b][j], u64 covers j pair (aligned, even offsets)
        {
            float* base = p_s + kz * PB + (tx * 2) * PBS + ty * 8;
            *(ull*)(base + 0) = acc00;  *(ull*)(base + PBS + 0) = acc01;
            *(ull*)(base + 2) = acc10;  *(ull*)(base + PBS + 2) = acc11;
            *(ull*)(base + 4) = acc20;  *(ull*)(base + PBS + 4) = acc21;
            *(ull*)(base + 6) = acc30;  *(ull*)(base + PBS + 6) = acc31;
        }
        __syncthreads();

        // reduce 8 k-slice partials + P, tanh, write h (sector-exact STG)
        {
            float s1 = p1, s2 = p2;
#pragma unroll
            for (int z = 0; z < KZ; z++) {
                s1 += p_s[z * PB + bl * PBS + jl1];
                s2 += p_s[z * PB + bl * PBS + jl2];
            }
            wbuf[(j0 + jl1) * B + b0 + bl] = tanhf(s1);
            wbuf[(j0 + jl2) * B + b0 + bl] = tanhf(s2);
        }

        // group barrier: release-add + acquire-spin (no threadfence / L1 flush)
        __syncthreads();
        if (tid == 0) {
            asm volatile("red.release.gpu.global.add.u32 [%0], 1;"
                         :: "l"(ctr) : "memory");
            unsigned v;
            unsigned target = (unsigned)(t + 1) * NJ;
            do {
                asm volatile("ld.acquire.gpu.u32 %0, [%1];"
                             : "=r"(v) : "l"(ctr) : "memory");
            } while (v < target);
        }
        __syncthreads();
    }
}

// ---------------- Phase C: output projection + hidden emit ----------------
__global__ void __launch_bounds__(256) phaseC_kernel(
    const float* __restrict__ Wh2o, const float* __restrict__ bh2o,
    float* __restrict__ out, int out_size) {
    const float* hfin = g_Hbuf[S & 1];       // buffer written at final step
    int idx = blockIdx.x * 256 + threadIdx.x;  // 0..32767
    int o = idx >> 7, b = idx & 127;         // lanes span b -> hfin coalesced
    float acc = bh2o[o];
#pragma unroll 8
    for (int k = 0; k < H; k++) {
        acc = fmaf(hfin[k * B + b], __ldg(Wh2o + (size_t)o * H + k), acc);
    }
    int oidx = b * O + o;                    // output (B,1,O)
    if (oidx < out_size) out[oidx] = acc;
    if (out_size >= B * O + B * H) {
#pragma unroll
        for (int q = 0; q < 2; q++) {
            int e = idx + q * (B * O);       // 0..65535
            int hb = e >> 9, hk = e & 511;
            out[B * O + e] = hfin[hk * B + hb];
        }
    }
}

extern "C" void kernel_launch(void* const* d_in, const int* in_sizes, int n_in,
                              void* d_out, int out_size) {
    const float* seq  = (const float*)d_in[0];
    const float* Wi2h = (const float*)d_in[1];
    const float* bi2h = (const float*)d_in[2];
    const float* Wh2o = (const float*)d_in[3];
    const float* bh2o = (const float*)d_in[4];
    float* out = (float*)d_out;

    cudaFuncSetAttribute(phaseB_kernel,
                         cudaFuncAttributeMaxDynamicSharedMemorySize, SMEM_B_BYTES);

    void* pBar = nullptr;
    cudaGetSymbolAddress(&pBar, g_bar);
    cudaMemsetAsync(pBar, 0, sizeof(g_bar), 0);
    void* pH = nullptr;
    cudaGetSymbolAddress(&pH, g_Hbuf);
    cudaMemsetAsync(pH, 0, (size_t)H * B * sizeof(float), 0);  // buf[0] = h0 = 0

    phaseA_kernel<<<dim3(S, H / 128), 256>>>(seq, Wi2h, bi2h);
    phaseB_kernel<<<NJ * NB, 256, SMEM_B_BYTES>>>(Wi2h);
    phaseC_kernel<<<(B * O) / 256, 256>>>(Wh2o, bh2o, out, out_size);
}